// round 15
// baseline (speedup 1.0000x reference)
#include <cuda_runtime.h>
#include <cuda_fp16.h>
#include <cstdint>

#define BB   128      // batch
#define TT   512      // time
#define DIN  512      // input dim (also 2H for layer 1)
#define HH   256      // hidden
#define G4   1024     // 4*H
#define MM   (TT*BB)  // 65536 rows of A

#define HN_OFF 33554432ULL              // B*T*512
#define CN_OFF (HN_OFF + 131072ULL)     // + 4*B*H

// ---------------- device scratch (static, no runtime alloc) ----------------
// Row ordering is b-major: row m = b*TT + t  (matches x's native (B,T,D) order)
__device__ __align__(256) __half g_xh[(size_t)MM * DIN];   // x fp16 (B,T,D)
__device__ __align__(256) __half g_i2h[(size_t)MM * DIN];  // layer-1 input fp16
__device__ __align__(256) __half g_w[4ULL * G4 * DIN];     // permuted W_ih (fp16)
__device__ __align__(256) float g_bias[4 * G4];            // permuted b_ih+b_hh
__device__ __align__(256) float g_xproj[2ULL * TT * BB * G4];  // gate preacts (b-major)

// ---------------- small helpers --------------------------------------------
__device__ __forceinline__ float tanhfast(float x) {
    float y; asm("tanh.approx.f32 %0, %1;" : "=f"(y) : "f"(x)); return y;
}
__device__ __forceinline__ float sigmfast(float x) {
    return fmaf(0.5f, tanhfast(0.5f * x), 0.5f);
}
__device__ __forceinline__ uint32_t smem_u32(const void* p) {
    uint32_t a;
    asm("{ .reg .u64 t; cvta.to.shared.u64 t, %1; cvt.u32.u64 %0, t; }" : "=r"(a) : "l"(p));
    return a;
}

// ---------------- mma.sync / ldmatrix / cp.async / cluster wrappers ---------
__device__ __forceinline__ void ldm4(uint32_t* r, uint32_t addr) {
    asm volatile("ldmatrix.sync.aligned.m8n8.x4.shared.b16 {%0,%1,%2,%3}, [%4];"
                 : "=r"(r[0]), "=r"(r[1]), "=r"(r[2]), "=r"(r[3]) : "r"(addr));
}
__device__ __forceinline__ void mma_f16(float* d, const uint32_t* a,
                                        uint32_t b0, uint32_t b1) {
    asm volatile(
        "mma.sync.aligned.m16n8k16.row.col.f32.f16.f16.f32 "
        "{%0,%1,%2,%3}, {%4,%5,%6,%7}, {%8,%9}, {%0,%1,%2,%3};"
        : "+f"(d[0]), "+f"(d[1]), "+f"(d[2]), "+f"(d[3])
        : "r"(a[0]), "r"(a[1]), "r"(a[2]), "r"(a[3]), "r"(b0), "r"(b1));
}
__device__ __forceinline__ void cpasync16(uint32_t dst, const void* src) {
    asm volatile("cp.async.cg.shared.global [%0], [%1], 16;" :: "r"(dst), "l"(src));
}
#define CP_COMMIT() asm volatile("cp.async.commit_group;" ::: "memory")
#define CP_WAIT(n)  asm volatile("cp.async.wait_group %0;" :: "n"(n) : "memory")
#define CLU_ARRIVE() asm volatile("barrier.cluster.arrive.aligned;" ::: "memory")
#define CLU_WAIT()   asm volatile("barrier.cluster.wait.aligned;" ::: "memory")
__device__ __forceinline__ uint32_t mapa_u32(uint32_t laddr, uint32_t rank) {
    uint32_t r;
    asm volatile("mapa.shared::cluster.u32 %0, %1, %2;" : "=r"(r) : "r"(laddr), "r"(rank));
    return r;
}
__device__ __forceinline__ void st_clu(uint32_t addr, uint32_t v) {
    asm volatile("st.shared::cluster.u32 [%0], %1;" :: "r"(addr), "r"(v));
}

// ---------------- zero the output sequence region ----------------------------
__global__ void k_zero_out(float* __restrict__ dout)
{
    size_t i = (size_t)blockIdx.x * blockDim.x + threadIdx.x;   // float4 index
    if (i < HN_OFF / 4)
        ((float4*)dout)[i] = make_float4(0.f, 0.f, 0.f, 0.f);
}

// ---------------- convert x: (B,T,D) fp32 -> fp16, same order ---------------
__global__ void k_split_x(const float* __restrict__ x)
{
    int i = blockIdx.x * blockDim.x + threadIdx.x;       // float4 index
    const int N4 = MM * (DIN / 4);
    if (i >= N4) return;
    float4 v = ((const float4*)x)[i];
    __half h[4];
    h[0] = __float2half_rn(v.x); h[1] = __float2half_rn(v.y);
    h[2] = __float2half_rn(v.z); h[3] = __float2half_rn(v.w);
    ((uint2*)g_xh)[i] = *(uint2*)h;
}

// ---------------- convert + permute weights (fp16 single) -------------------
__global__ void k_split_w(const float* __restrict__ Wih, const float* __restrict__ bih,
                          const float* __restrict__ bhh)
{
    int i = blockIdx.x * blockDim.x + threadIdx.x;       // (ld, n, k4)
    if (i >= 4 * G4 * (DIN / 4)) return;
    int k4 = i & 127;
    int rest = i >> 7;
    int n = rest & (G4 - 1);
    int ld = rest >> 10;
    int r = (n & 3) * HH + (n >> 2);
    float4 v = *(const float4*)(Wih + ((size_t)ld * G4 + r) * DIN + k4 * 4);
    __half h[4];
    h[0] = __float2half_rn(v.x); h[1] = __float2half_rn(v.y);
    h[2] = __float2half_rn(v.z); h[3] = __float2half_rn(v.w);
    size_t off = ((size_t)ld * G4 + n) * DIN + k4 * 4;
    *(uint2*)(g_w + off) = *(uint2*)h;
    if (k4 == 0)
        g_bias[ld * G4 + n] = bih[ld * G4 + r] + bhh[ld * G4 + r];
}

// ---------------- mma.sync input-projection GEMM (fp16, 4-stage pipeline) ----
#define KC     32
#define NCH    (DIN / KC)                  // 16 chunks
#define LDS_T  40
#define ARR_B  (128 * LDS_T * 2)           // 10240
#define STG_B  (2 * ARR_B)                 // 20480  (A + W)
#define SMO_BIAS  0
#define SMO_TILES 512
#define SM_GEMM   (SMO_TILES + 4 * STG_B)  // 82432

__global__ void __launch_bounds__(256, 2) k_gemm_tc(const int* __restrict__ lengths,
                                                    int layer)
{
    const int mb  = blockIdx.y * 128;
    // tile-skip: rows are b-major (m = b*TT + t); a 128-row tile spans one b.
    {
        int b = mb >> 9;
        int t0 = mb & (TT - 1);
        if (t0 >= lengths[b]) return;     // xproj never unmasked -> skip
    }

    extern __shared__ char smx[];
    const uint32_t smb = smem_u32(smx);
    const int tid = threadIdx.x;
    const int lane = tid & 31;
    const int w   = tid >> 5;
    const int wm  = w & 1;
    const int wn  = w >> 1;
    const int dir = blockIdx.z;
    const int nb  = blockIdx.x * 128;

    const __half* Ah = layer ? g_i2h : g_xh;
    const __half* Wd = g_w + (size_t)(layer * 2 + dir) * G4 * DIN;

    float* bs = (float*)(smx + SMO_BIAS);
    if (tid < 128) bs[tid] = g_bias[(layer * 2 + dir) * G4 + nb + tid];

    auto issue_stage = [&](int ch) {
        const int kc = ch * KC;
        const uint32_t sb = smb + SMO_TILES + (ch & 3) * STG_B;
#pragma unroll
        for (int j = 0; j < 4; j++) {
            int c = tid + j * 256;
            int arr = c >> 9, rem = c & 511, row = rem >> 2, ck = rem & 3;
            uint32_t dst = sb + arr * ARR_B + row * (LDS_T * 2) + ck * 16;
            const __half* src = (arr == 0)
                ? Ah + (size_t)(mb + row) * DIN + kc + ck * 8
                : Wd + (size_t)(nb + row) * DIN + kc + ck * 8;
            cpasync16(dst, src);
        }
        CP_COMMIT();
    };

    issue_stage(0);
    issue_stage(1);

    float acc[4][4][4];
#pragma unroll
    for (int mi = 0; mi < 4; mi++)
#pragma unroll
        for (int ni = 0; ni < 4; ni++)
#pragma unroll
            for (int q = 0; q < 4; q++) acc[mi][ni][q] = 0.f;

    // pair-wise consumption: wait -> sync -> issue next pair -> consume pair.
    // One __syncthreads per 2 chunks; copies of the next pair overlap this
    // pair's mma. Sync AFTER wait gives cross-thread cp.async visibility.
    for (int cp = 0; cp < NCH; cp += 2) {
        CP_WAIT(0);            // this thread's chunks cp, cp+1 have landed
        __syncthreads();       // everyone's copies visible; old buffers free
        if (cp + 2 < NCH) issue_stage(cp + 2);
        if (cp + 3 < NCH) issue_stage(cp + 3);

#pragma unroll
        for (int ci = 0; ci < 2; ci++) {
            const int ch = cp + ci;
            const uint32_t sA = smb + SMO_TILES + (ch & 3) * STG_B;
            const uint32_t sB = sA + ARR_B;

#pragma unroll
            for (int ks = 0; ks < 2; ks++) {
                const int k0 = ks * 16;
                const uint32_t aoff = ((lane & 15) * LDS_T + k0 + (lane >> 4) * 8) * 2;
                uint32_t ah[4][4];
#pragma unroll
                for (int mi = 0; mi < 4; mi++) {
                    uint32_t ro = (wm * 64 + mi * 16) * (LDS_T * 2);
                    ldm4(ah[mi], sA + ro + aoff);
                }
                uint32_t bh[2][4];
#pragma unroll
                for (int nj = 0; nj < 2; nj++) {
                    uint32_t ro = (wn * 32 + nj * 16) * (LDS_T * 2);
                    ldm4(bh[nj], sB + ro + aoff);
                }
#pragma unroll
                for (int mi = 0; mi < 4; mi++)
#pragma unroll
                    for (int ni = 0; ni < 4; ni++) {
                        int nj = ni >> 1, hf = ni & 1;
                        mma_f16(acc[mi][ni], ah[mi], bh[nj][hf], bh[nj][hf + 2]);
                    }
            }
        }
    }
    __syncthreads();

    float* xp = g_xproj + (size_t)dir * TT * BB * G4;
    const int gid = lane >> 2, tig = lane & 3;
#pragma unroll
    for (int mi = 0; mi < 4; mi++) {
#pragma unroll
        for (int ni = 0; ni < 4; ni++) {
            int col = wn * 32 + ni * 8 + tig * 2;
            float b0 = bs[col], b1 = bs[col + 1];
            int r0 = mb + wm * 64 + mi * 16 + gid;
            float2 v0 = make_float2(acc[mi][ni][0] + b0, acc[mi][ni][1] + b1);
            float2 v1 = make_float2(acc[mi][ni][2] + b0, acc[mi][ni][3] + b1);
            *(float2*)(xp + (size_t)r0 * G4 + nb + col) = v0;
            *(float2*)(xp + (size_t)(r0 + 8) * G4 + nb + col) = v1;
        }
    }
}

// ---------------- recurrent persistent kernel (cluster + DSMEM, 16 warps) ----
// grid = 2 dir x 8 bgroup (M=16) x 8 nslice (N=128).  Cluster = the 8 nslices.
// Step-skip: lengths sorted desc -> group max = lengths[mg*16]; steps beyond it
// are provable no-ops in both directions (mask false for entire group).
#define RLDS  264                          // padded row stride (fp16 elems)
#define OW_S  0                            // W slice: 128 x 256 fp16 = 67584
#define AB_SZ (16 * RLDS * 2)              // 8448 per A buffer
#define OA_H0 (OW_S + 128 * RLDS * 2)      // 67584
#define OA_H1 (OA_H0 + AB_SZ)              // 76032
#define OS_S  (OA_H1 + AB_SZ)              // 84480  S:  16 x 132 f32
#define OS_S2 (OS_S + 16 * 132 * 4)        // 92928  S2: 16 x 132 f32
#define SM_REC (OS_S2 + 16 * 132 * 4)      // 101376

__global__ void __launch_bounds__(512) __cluster_dims__(8, 1, 1)
k_lstm(const float* __restrict__ Whh, const int* __restrict__ lengths,
       float* __restrict__ dout, int layer)
{
    extern __shared__ char smx[];
    const uint32_t smb = smem_u32(smx);
    float* S  = (float*)(smx + OS_S);
    float* S2 = (float*)(smx + OS_S2);

    const int cid = blockIdx.x >> 3;      // cluster id 0..15
    const int dir = cid >> 3;             // 0..1
    const int mg  = cid & 7;              // batch group 0..7 (M=16)
    const int ns  = blockIdx.x & 7;       // n-slice (== cluster ctarank)
    const int tid = threadIdx.x;
    const int lane = tid & 31;
    const int wid  = tid >> 5;            // 0..15
    const int wn2  = wid & 7;             // 16-col slice
    const int kh   = wid >> 3;            // K half 0/1
    const int gid = lane >> 2, tig = lane & 3;

    const float* W = Whh + (size_t)(layer * 2 + dir) * G4 * HH;

    // resident W_hh slice (128 gate cols x 256) -> smem fp16, once
    for (int idx = tid; idx < 128 * 256; idx += 512) {
        int nl = idx >> 8; int k = idx & 255;
        int n = ns * 128 + nl;
        int row = (n & 3) * HH + (n >> 2);
        *(__half*)(smx + OW_S + (nl * RLDS + k) * 2) = __float2half_rn(W[(size_t)row * HH + k]);
    }
    // zero both parities of A
    for (int idx = tid; idx < 2 * AB_SZ / 4; idx += 512)
        *(uint32_t*)(smx + OA_H0 + idx * 4) = 0;
    __syncthreads();

    // hoist W fragments: this warp's 16 cols x its K-half (8 k-iters)
    const uint32_t aoff = ((lane & 15) * RLDS + (lane >> 4) * 8 + kh * 128) * 2;
    const uint32_t bbase = (uint32_t)(wn2 * 16 * RLDS * 2);
    uint32_t bf[8][4];
#pragma unroll
    for (int ki = 0; ki < 8; ki++)
        ldm4(bf[ki], smb + OW_S + bbase + aoff + ki * 32);

    // pointwise mapping: unit u = lane (0..31), batch m = wid (0..15)
    const int u = lane;
    const int m = wid;
    const int b_glob = mg * 16 + m;
    const int u0g = ns * 32 + u;          // global unit col in A
    const int len = lengths[b_glob];

    // group-uniform step count: lengths sorted desc -> max of group = first elem
    const int steps = lengths[mg * 16];

    float cs = 0.f, hs = 0.f;

    const float* xpbase = g_xproj + (size_t)dir * TT * BB * G4;

    float4 pg;
    {
        int t0 = dir ? (steps - 1) : 0;
        pg = *(const float4*)(xpbase + ((size_t)b_glob * TT + t0) * G4 + u0g * 4);
    }

    const uint32_t laddr_off = (m * RLDS + u0g) * 2;   // even-lane threads push

    CLU_ARRIVE(); CLU_WAIT();   // zeroed A visible cluster-wide

    for (int s = 0; s < steps; s++) {
        int t = dir ? (steps - 1 - s) : s;
        const uint32_t pA = smb + ((s & 1) ? OA_H1 : OA_H0);

        // mma: partial S[16 x 128] over this warp's K half
        float acc[2][4];
#pragma unroll
        for (int ni = 0; ni < 2; ni++)
#pragma unroll
            for (int q = 0; q < 4; q++) acc[ni][q] = 0.f;

#pragma unroll
        for (int ki = 0; ki < 8; ki++) {
            uint32_t ah[4];
            ldm4(ah, pA + aoff + ki * 32);
            mma_f16(acc[0], ah, bf[ki][0], bf[ki][2]);
            mma_f16(acc[1], ah, bf[ki][1], bf[ki][3]);
        }

        // partial accumulators -> S (k-half 0) / S2 (k-half 1)
        float* Sk = kh ? S2 : S;
#pragma unroll
        for (int ni = 0; ni < 2; ni++) {
            int col = wn2 * 16 + ni * 8 + tig * 2;
            *(float2*)&Sk[gid * 132 + col] = make_float2(acc[ni][0], acc[ni][1]);
            *(float2*)&Sk[(gid + 8) * 132 + col] = make_float2(acc[ni][2], acc[ni][3]);
        }
        __syncthreads();

        // pointwise: 1 (batch m, unit u) per thread
        const bool val = (t < len);
        float4 s1 = *(const float4*)&S[m * 132 + u * 4];
        float4 s2 = *(const float4*)&S2[m * 132 + u * 4];
        float gi = sigmfast(s1.x + s2.x + pg.x);
        float gf = sigmfast(s1.y + s2.y + pg.y);
        float gg = tanhfast(s1.z + s2.z + pg.z);
        float go = sigmfast(s1.w + s2.w + pg.w);
        float cn = gf * cs + gi * gg;
        float hn = go * tanhfast(cn);
        if (val) { cs = cn; hs = hn; }
        float ov = val ? hn : 0.f;

        // pack pairs via shuffle (even lane owns units u, u+1)
        float hs2 = __shfl_down_sync(0xffffffffu, hs, 1);
        float ov2 = __shfl_down_sync(0xffffffffu, ov, 1);
        uint32_t vh = (uint32_t)__half_as_ushort(__float2half_rn(hs)) |
                      ((uint32_t)__half_as_ushort(__float2half_rn(hs2)) << 16);
        uint32_t vo = (uint32_t)__half_as_ushort(__float2half_rn(ov)) |
                      ((uint32_t)__half_as_ushort(__float2half_rn(ov2)) << 16);

        // push h (2 units = 1 u32) into all 8 cluster CTAs' A[p^1]
        if (!(lane & 1)) {
            uint32_t la = smb + ((s & 1) ? OA_H0 : OA_H1) + laddr_off;
#pragma unroll
            for (uint32_t r = 0; r < 8; r++)
                st_clu(mapa_u32(la, r), vh);
        }

        CLU_ARRIVE();   // pushes ordered/released; overlap global work with skew

        if (layer == 0) {
            if (!(lane & 1)) {
                size_t off = ((size_t)b_glob * TT + t) * DIN + dir * HH + u0g;
                *(uint32_t*)(g_i2h + off) = vo;
            }
        } else {
            dout[((size_t)b_glob * TT + t) * 512 + dir * HH + u0g] = ov;
        }
        if (s + 1 < steps) {
            int t2 = dir ? (steps - 2 - s) : (s + 1);
            pg = *(const float4*)(xpbase + ((size_t)b_glob * TT + t2) * G4 + u0g * 4);
        }

        CLU_WAIT();     // peers' pushes visible; also full block barrier
    }

    // final h_n / c_n (coalesced: lane-major units)
    {
        size_t o = (size_t)((layer * 2 + dir) * BB + b_glob) * HH + u0g;
        dout[HN_OFF + o] = hs;
        dout[CN_OFF + o] = cs;
    }
}

// ---------------- launch -----------------------------------------------------
extern "C" void kernel_launch(void* const* d_in, const int* in_sizes, int n_in,
                              void* d_out, int out_size)
{
    const float* x   = (const float*)d_in[0];
    const int*   len = (const int*)d_in[1];
    const float* Wih = (const float*)d_in[2];
    const float* Whh = (const float*)d_in[3];
    const float* bih = (const float*)d_in[4];
    const float* bhh = (const float*)d_in[5];
    float* out = (float*)d_out;

    cudaFuncSetAttribute(k_lstm, cudaFuncAttributeMaxDynamicSharedMemorySize, SM_REC);
    cudaFuncSetAttribute(k_gemm_tc, cudaFuncAttributeMaxDynamicSharedMemorySize, SM_GEMM);

    // zero the output sequence region (skipped steps must read as 0)
    k_zero_out<<<(unsigned)((HN_OFF / 4 + 1023) / 1024), 1024>>>(out);

    k_split_x<<<(MM * (DIN / 4) + 255) / 256, 256>>>(x);
    k_split_w<<<(4 * G4 * (DIN / 4) + 255) / 256, 256>>>(Wih, bih, bhh);

    k_gemm_tc<<<dim3(G4 / 128, MM / 128, 2), 256, SM_GEMM>>>(len, 0);
    k_lstm<<<128, 512, SM_REC>>>(Whh, len, out, 0);
    k_gemm_tc<<<dim3(G4 / 128, MM / 128, 2), 256, SM_GEMM>>>(len, 1);
    k_lstm<<<128, 512, SM_REC>>>(Whh, len, out, 1);
}

// round 16
// speedup vs baseline: 1.0068x; 1.0068x over previous
#include <cuda_runtime.h>
#include <cuda_fp16.h>
#include <cstdint>

#define BB   128      // batch
#define TT   512      // time
#define DIN  512      // input dim (also 2H for layer 1)
#define HH   256      // hidden
#define G4   1024     // 4*H
#define MM   (TT*BB)  // 65536 rows of A

#define HN_OFF 33554432ULL              // B*T*512
#define CN_OFF (HN_OFF + 131072ULL)     // + 4*B*H

// ---------------- device scratch (static, no runtime alloc) ----------------
// Row ordering is b-major: row m = b*TT + t  (matches x's native (B,T,D) order)
__device__ __align__(256) __half g_xh[(size_t)MM * DIN];   // x fp16 (B,T,D)
__device__ __align__(256) __half g_i2h[(size_t)MM * DIN];  // layer-1 input fp16
__device__ __align__(256) __half g_w[4ULL * G4 * DIN];     // permuted W_ih (fp16)
__device__ __align__(256) float g_bias[4 * G4];            // permuted b_ih+b_hh
__device__ __align__(256) float g_xproj[2ULL * TT * BB * G4];  // gate preacts (b-major)

// ---------------- small helpers --------------------------------------------
__device__ __forceinline__ float tanhfast(float x) {
    float y; asm("tanh.approx.f32 %0, %1;" : "=f"(y) : "f"(x)); return y;
}
__device__ __forceinline__ float sigmfast(float x) {
    return fmaf(0.5f, tanhfast(0.5f * x), 0.5f);
}
__device__ __forceinline__ uint32_t smem_u32(const void* p) {
    uint32_t a;
    asm("{ .reg .u64 t; cvta.to.shared.u64 t, %1; cvt.u32.u64 %0, t; }" : "=r"(a) : "l"(p));
    return a;
}

// ---------------- mma.sync / ldmatrix / cp.async / cluster wrappers ---------
__device__ __forceinline__ void ldm4(uint32_t* r, uint32_t addr) {
    asm volatile("ldmatrix.sync.aligned.m8n8.x4.shared.b16 {%0,%1,%2,%3}, [%4];"
                 : "=r"(r[0]), "=r"(r[1]), "=r"(r[2]), "=r"(r[3]) : "r"(addr));
}
__device__ __forceinline__ void mma_f16(float* d, const uint32_t* a,
                                        uint32_t b0, uint32_t b1) {
    asm volatile(
        "mma.sync.aligned.m16n8k16.row.col.f32.f16.f16.f32 "
        "{%0,%1,%2,%3}, {%4,%5,%6,%7}, {%8,%9}, {%0,%1,%2,%3};"
        : "+f"(d[0]), "+f"(d[1]), "+f"(d[2]), "+f"(d[3])
        : "r"(a[0]), "r"(a[1]), "r"(a[2]), "r"(a[3]), "r"(b0), "r"(b1));
}
__device__ __forceinline__ void cpasync16(uint32_t dst, const void* src) {
    asm volatile("cp.async.cg.shared.global [%0], [%1], 16;" :: "r"(dst), "l"(src));
}
#define CP_COMMIT() asm volatile("cp.async.commit_group;" ::: "memory")
#define CP_WAIT(n)  asm volatile("cp.async.wait_group %0;" :: "n"(n) : "memory")
#define CLU_ARRIVE() asm volatile("barrier.cluster.arrive.aligned;" ::: "memory")
#define CLU_WAIT()   asm volatile("barrier.cluster.wait.aligned;" ::: "memory")
__device__ __forceinline__ uint32_t mapa_u32(uint32_t laddr, uint32_t rank) {
    uint32_t r;
    asm volatile("mapa.shared::cluster.u32 %0, %1, %2;" : "=r"(r) : "r"(laddr), "r"(rank));
    return r;
}
__device__ __forceinline__ void st_clu(uint32_t addr, uint32_t v) {
    asm volatile("st.shared::cluster.u32 [%0], %1;" :: "r"(addr), "r"(v));
}

// ---------------- zero the output sequence region ----------------------------
__global__ void k_zero_out(float* __restrict__ dout)
{
    size_t i = (size_t)blockIdx.x * blockDim.x + threadIdx.x;   // float4 index
    if (i < HN_OFF / 4)
        ((float4*)dout)[i] = make_float4(0.f, 0.f, 0.f, 0.f);
}

// ---------------- convert x: (B,T,D) fp32 -> fp16, same order ---------------
__global__ void k_split_x(const float* __restrict__ x)
{
    int i = blockIdx.x * blockDim.x + threadIdx.x;       // float4 index
    const int N4 = MM * (DIN / 4);
    if (i >= N4) return;
    float4 v = ((const float4*)x)[i];
    __half h[4];
    h[0] = __float2half_rn(v.x); h[1] = __float2half_rn(v.y);
    h[2] = __float2half_rn(v.z); h[3] = __float2half_rn(v.w);
    ((uint2*)g_xh)[i] = *(uint2*)h;
}

// ---------------- convert + permute weights (fp16 single) -------------------
__global__ void k_split_w(const float* __restrict__ Wih, const float* __restrict__ bih,
                          const float* __restrict__ bhh)
{
    int i = blockIdx.x * blockDim.x + threadIdx.x;       // (ld, n, k4)
    if (i >= 4 * G4 * (DIN / 4)) return;
    int k4 = i & 127;
    int rest = i >> 7;
    int n = rest & (G4 - 1);
    int ld = rest >> 10;
    int r = (n & 3) * HH + (n >> 2);
    float4 v = *(const float4*)(Wih + ((size_t)ld * G4 + r) * DIN + k4 * 4);
    __half h[4];
    h[0] = __float2half_rn(v.x); h[1] = __float2half_rn(v.y);
    h[2] = __float2half_rn(v.z); h[3] = __float2half_rn(v.w);
    size_t off = ((size_t)ld * G4 + n) * DIN + k4 * 4;
    *(uint2*)(g_w + off) = *(uint2*)h;
    if (k4 == 0)
        g_bias[ld * G4 + n] = bih[ld * G4 + r] + bhh[ld * G4 + r];
}

// ---------------- mma.sync input-projection GEMM (fp16, 4-stage, R13 order) --
#define KC     32
#define NCH    (DIN / KC)                  // 16 chunks
#define LDS_T  40
#define ARR_B  (128 * LDS_T * 2)           // 10240
#define STG_B  (2 * ARR_B)                 // 20480  (A + W)
#define SMO_BIAS  0
#define SMO_TILES 512
#define SM_GEMM   (SMO_TILES + 4 * STG_B)  // 82432

__global__ void __launch_bounds__(256, 2) k_gemm_tc(const int* __restrict__ lengths,
                                                    int layer)
{
    const int mb  = blockIdx.y * 128;
    // tile-skip: rows are b-major (m = b*TT + t); a 128-row tile spans one b.
    {
        int b = mb >> 9;
        int t0 = mb & (TT - 1);
        if (t0 >= lengths[b]) return;     // xproj never unmasked -> skip
    }

    extern __shared__ char smx[];
    const uint32_t smb = smem_u32(smx);
    const int tid = threadIdx.x;
    const int lane = tid & 31;
    const int w   = tid >> 5;
    const int wm  = w & 1;
    const int wn  = w >> 1;
    const int dir = blockIdx.z;
    const int nb  = blockIdx.x * 128;

    const __half* Ah = layer ? g_i2h : g_xh;
    const __half* Wd = g_w + (size_t)(layer * 2 + dir) * G4 * DIN;

    float* bs = (float*)(smx + SMO_BIAS);
    if (tid < 128) bs[tid] = g_bias[(layer * 2 + dir) * G4 + nb + tid];

    auto issue_stage = [&](int ch) {
        const int kc = ch * KC;
        const uint32_t sb = smb + SMO_TILES + (ch & 3) * STG_B;
#pragma unroll
        for (int j = 0; j < 4; j++) {
            int c = tid + j * 256;
            int arr = c >> 9, rem = c & 511, row = rem >> 2, ck = rem & 3;
            uint32_t dst = sb + arr * ARR_B + row * (LDS_T * 2) + ck * 16;
            const __half* src = (arr == 0)
                ? Ah + (size_t)(mb + row) * DIN + kc + ck * 8
                : Wd + (size_t)(nb + row) * DIN + kc + ck * 8;
            cpasync16(dst, src);
        }
        CP_COMMIT();
    };

    issue_stage(0);
    issue_stage(1);
    issue_stage(2);

    float acc[4][4][4];
#pragma unroll
    for (int mi = 0; mi < 4; mi++)
#pragma unroll
        for (int ni = 0; ni < 4; ni++)
#pragma unroll
            for (int q = 0; q < 4; q++) acc[mi][ni][q] = 0.f;

    // R13 ordering, deeper queue: wait(2) -> sync -> issue ch+3 -> consume ch.
    // 3 chunks stay in flight during every consume.
    for (int ch = 0; ch < NCH; ch++) {
        if (ch + 2 < NCH)      { CP_WAIT(2); }
        else if (ch + 1 < NCH) { CP_WAIT(1); }
        else                   { CP_WAIT(0); }
        __syncthreads();                       // ch visible to all; (ch-1)&3 free
        if (ch + 3 < NCH) issue_stage(ch + 3);

        const uint32_t sA = smb + SMO_TILES + (ch & 3) * STG_B;
        const uint32_t sB = sA + ARR_B;

#pragma unroll
        for (int ks = 0; ks < 2; ks++) {
            const int k0 = ks * 16;
            const uint32_t aoff = ((lane & 15) * LDS_T + k0 + (lane >> 4) * 8) * 2;
            uint32_t ah[4][4];
#pragma unroll
            for (int mi = 0; mi < 4; mi++) {
                uint32_t ro = (wm * 64 + mi * 16) * (LDS_T * 2);
                ldm4(ah[mi], sA + ro + aoff);
            }
            uint32_t bh[2][4];
#pragma unroll
            for (int nj = 0; nj < 2; nj++) {
                uint32_t ro = (wn * 32 + nj * 16) * (LDS_T * 2);
                ldm4(bh[nj], sB + ro + aoff);
            }
#pragma unroll
            for (int mi = 0; mi < 4; mi++)
#pragma unroll
                for (int ni = 0; ni < 4; ni++) {
                    int nj = ni >> 1, hf = ni & 1;
                    mma_f16(acc[mi][ni], ah[mi], bh[nj][hf], bh[nj][hf + 2]);
                }
        }
    }
    __syncthreads();

    float* xp = g_xproj + (size_t)dir * TT * BB * G4;
    const int gid = lane >> 2, tig = lane & 3;
#pragma unroll
    for (int mi = 0; mi < 4; mi++) {
#pragma unroll
        for (int ni = 0; ni < 4; ni++) {
            int col = wn * 32 + ni * 8 + tig * 2;
            float b0 = bs[col], b1 = bs[col + 1];
            int r0 = mb + wm * 64 + mi * 16 + gid;
            float2 v0 = make_float2(acc[mi][ni][0] + b0, acc[mi][ni][1] + b1);
            float2 v1 = make_float2(acc[mi][ni][2] + b0, acc[mi][ni][3] + b1);
            *(float2*)(xp + (size_t)r0 * G4 + nb + col) = v0;
            *(float2*)(xp + (size_t)(r0 + 8) * G4 + nb + col) = v1;
        }
    }
}

// ---------------- recurrent persistent kernel (cluster + DSMEM, 16 warps) ----
// grid = 2 dir x 8 bgroup (M=16) x 8 nslice (N=128).  Cluster = the 8 nslices.
// Step-skip: lengths sorted desc -> group max = lengths[mg*16]; steps beyond it
// are provable no-ops in both directions (mask false for entire group).
#define RLDS  264                          // padded row stride (fp16 elems)
#define OW_S  0                            // W slice: 128 x 256 fp16 = 67584
#define AB_SZ (16 * RLDS * 2)              // 8448 per A buffer
#define OA_H0 (OW_S + 128 * RLDS * 2)      // 67584
#define OA_H1 (OA_H0 + AB_SZ)              // 76032
#define OS_S  (OA_H1 + AB_SZ)              // 84480  S:  16 x 132 f32
#define OS_S2 (OS_S + 16 * 132 * 4)        // 92928  S2: 16 x 132 f32
#define SM_REC (OS_S2 + 16 * 132 * 4)      // 101376

__global__ void __launch_bounds__(512) __cluster_dims__(8, 1, 1)
k_lstm(const float* __restrict__ Whh, const int* __restrict__ lengths,
       float* __restrict__ dout, int layer)
{
    extern __shared__ char smx[];
    const uint32_t smb = smem_u32(smx);
    float* S  = (float*)(smx + OS_S);
    float* S2 = (float*)(smx + OS_S2);

    const int cid = blockIdx.x >> 3;      // cluster id 0..15
    const int dir = cid >> 3;             // 0..1
    const int mg  = cid & 7;              // batch group 0..7 (M=16)
    const int ns  = blockIdx.x & 7;       // n-slice (== cluster ctarank)
    const int tid = threadIdx.x;
    const int lane = tid & 31;
    const int wid  = tid >> 5;            // 0..15
    const int wn2  = wid & 7;             // 16-col slice
    const int kh   = wid >> 3;            // K half 0/1
    const int gid = lane >> 2, tig = lane & 3;

    const float* W = Whh + (size_t)(layer * 2 + dir) * G4 * HH;

    // resident W_hh slice (128 gate cols x 256) -> smem fp16, once
    for (int idx = tid; idx < 128 * 256; idx += 512) {
        int nl = idx >> 8; int k = idx & 255;
        int n = ns * 128 + nl;
        int row = (n & 3) * HH + (n >> 2);
        *(__half*)(smx + OW_S + (nl * RLDS + k) * 2) = __float2half_rn(W[(size_t)row * HH + k]);
    }
    // zero both parities of A
    for (int idx = tid; idx < 2 * AB_SZ / 4; idx += 512)
        *(uint32_t*)(smx + OA_H0 + idx * 4) = 0;
    __syncthreads();

    // hoist W fragments: this warp's 16 cols x its K-half (8 k-iters)
    const uint32_t aoff = ((lane & 15) * RLDS + (lane >> 4) * 8 + kh * 128) * 2;
    const uint32_t bbase = (uint32_t)(wn2 * 16 * RLDS * 2);
    uint32_t bf[8][4];
#pragma unroll
    for (int ki = 0; ki < 8; ki++)
        ldm4(bf[ki], smb + OW_S + bbase + aoff + ki * 32);

    // pointwise mapping: unit u = lane (0..31), batch m = wid (0..15)
    const int u = lane;
    const int m = wid;
    const int b_glob = mg * 16 + m;
    const int u0g = ns * 32 + u;          // global unit col in A
    const int len = lengths[b_glob];

    // group-uniform step count: lengths sorted desc -> max of group = first elem
    const int steps = lengths[mg * 16];

    float cs = 0.f, hs = 0.f;

    const float* xpbase = g_xproj + (size_t)dir * TT * BB * G4;

    float4 pg;
    {
        int t0 = dir ? (steps - 1) : 0;
        pg = *(const float4*)(xpbase + ((size_t)b_glob * TT + t0) * G4 + u0g * 4);
    }

    const uint32_t laddr_off = (m * RLDS + u0g) * 2;   // even-lane threads push

    CLU_ARRIVE(); CLU_WAIT();   // zeroed A visible cluster-wide

    for (int s = 0; s < steps; s++) {
        int t = dir ? (steps - 1 - s) : s;
        const uint32_t pA = smb + ((s & 1) ? OA_H1 : OA_H0);

        // mma: partial S[16 x 128] over this warp's K half
        float acc[2][4];
#pragma unroll
        for (int ni = 0; ni < 2; ni++)
#pragma unroll
            for (int q = 0; q < 4; q++) acc[ni][q] = 0.f;

#pragma unroll
        for (int ki = 0; ki < 8; ki++) {
            uint32_t ah[4];
            ldm4(ah, pA + aoff + ki * 32);
            mma_f16(acc[0], ah, bf[ki][0], bf[ki][2]);
            mma_f16(acc[1], ah, bf[ki][1], bf[ki][3]);
        }

        // partial accumulators -> S (k-half 0) / S2 (k-half 1)
        float* Sk = kh ? S2 : S;
#pragma unroll
        for (int ni = 0; ni < 2; ni++) {
            int col = wn2 * 16 + ni * 8 + tig * 2;
            *(float2*)&Sk[gid * 132 + col] = make_float2(acc[ni][0], acc[ni][1]);
            *(float2*)&Sk[(gid + 8) * 132 + col] = make_float2(acc[ni][2], acc[ni][3]);
        }
        __syncthreads();

        // pointwise: 1 (batch m, unit u) per thread
        const bool val = (t < len);
        float4 s1 = *(const float4*)&S[m * 132 + u * 4];
        float4 s2 = *(const float4*)&S2[m * 132 + u * 4];
        float gi = sigmfast(s1.x + s2.x + pg.x);
        float gf = sigmfast(s1.y + s2.y + pg.y);
        float gg = tanhfast(s1.z + s2.z + pg.z);
        float go = sigmfast(s1.w + s2.w + pg.w);
        float cn = gf * cs + gi * gg;
        float hn = go * tanhfast(cn);
        if (val) { cs = cn; hs = hn; }
        float ov = val ? hn : 0.f;

        // pack pairs via shuffle (even lane owns units u, u+1)
        float hs2 = __shfl_down_sync(0xffffffffu, hs, 1);
        float ov2 = __shfl_down_sync(0xffffffffu, ov, 1);
        uint32_t vh = (uint32_t)__half_as_ushort(__float2half_rn(hs)) |
                      ((uint32_t)__half_as_ushort(__float2half_rn(hs2)) << 16);
        uint32_t vo = (uint32_t)__half_as_ushort(__float2half_rn(ov)) |
                      ((uint32_t)__half_as_ushort(__float2half_rn(ov2)) << 16);

        // push h (2 units = 1 u32) into all 8 cluster CTAs' A[p^1]
        if (!(lane & 1)) {
            uint32_t la = smb + ((s & 1) ? OA_H0 : OA_H1) + laddr_off;
#pragma unroll
            for (uint32_t r = 0; r < 8; r++)
                st_clu(mapa_u32(la, r), vh);
        }

        CLU_ARRIVE();   // pushes ordered/released; overlap global work with skew

        if (layer == 0) {
            if (!(lane & 1)) {
                size_t off = ((size_t)b_glob * TT + t) * DIN + dir * HH + u0g;
                *(uint32_t*)(g_i2h + off) = vo;
            }
        } else {
            dout[((size_t)b_glob * TT + t) * 512 + dir * HH + u0g] = ov;
        }
        if (s + 1 < steps) {
            int t2 = dir ? (steps - 2 - s) : (s + 1);
            pg = *(const float4*)(xpbase + ((size_t)b_glob * TT + t2) * G4 + u0g * 4);
        }

        CLU_WAIT();     // peers' pushes visible; also full block barrier
    }

    // final h_n / c_n (coalesced: lane-major units)
    {
        size_t o = (size_t)((layer * 2 + dir) * BB + b_glob) * HH + u0g;
        dout[HN_OFF + o] = hs;
        dout[CN_OFF + o] = cs;
    }
}

// ---------------- launch -----------------------------------------------------
extern "C" void kernel_launch(void* const* d_in, const int* in_sizes, int n_in,
                              void* d_out, int out_size)
{
    const float* x   = (const float*)d_in[0];
    const int*   len = (const int*)d_in[1];
    const float* Wih = (const float*)d_in[2];
    const float* Whh = (const float*)d_in[3];
    const float* bih = (const float*)d_in[4];
    const float* bhh = (const float*)d_in[5];
    float* out = (float*)d_out;

    cudaFuncSetAttribute(k_lstm, cudaFuncAttributeMaxDynamicSharedMemorySize, SM_REC);
    cudaFuncSetAttribute(k_gemm_tc, cudaFuncAttributeMaxDynamicSharedMemorySize, SM_GEMM);

    // zero the output sequence region (skipped steps must read as 0)
    k_zero_out<<<(unsigned)((HN_OFF / 4 + 1023) / 1024), 1024>>>(out);

    k_split_x<<<(MM * (DIN / 4) + 255) / 256, 256>>>(x);
    k_split_w<<<(4 * G4 * (DIN / 4) + 255) / 256, 256>>>(Wih, bih, bhh);

    k_gemm_tc<<<dim3(G4 / 128, MM / 128, 2), 256, SM_GEMM>>>(len, 0);
    k_lstm<<<128, 512, SM_REC>>>(Whh, len, out, 0);
    k_gemm_tc<<<dim3(G4 / 128, MM / 128, 2), 256, SM_GEMM>>>(len, 1);
    k_lstm<<<128, 512, SM_REC>>>(Whh, len, out, 1);
}

// round 17
// speedup vs baseline: 1.0546x; 1.0475x over previous
#include <cuda_runtime.h>
#include <cuda_fp16.h>
#include <cstdint>

#define BB   128      // batch
#define TT   512      // time
#define DIN  512      // input dim (also 2H for layer 1)
#define HH   256      // hidden
#define G4   1024     // 4*H
#define MM   (TT*BB)  // 65536 rows of A

#define HN_OFF 33554432ULL              // B*T*512
#define CN_OFF (HN_OFF + 131072ULL)     // + 4*B*H

// ---------------- device scratch (static, no runtime alloc) ----------------
// Row ordering is b-major: row m = b*TT + t  (matches x's native (B,T,D) order)
__device__ __align__(256) __half g_xh[(size_t)MM * DIN];   // x fp16 (B,T,D)
__device__ __align__(256) __half g_i2h[(size_t)MM * DIN];  // layer-1 input fp16
__device__ __align__(256) __half g_w[4ULL * G4 * DIN];     // permuted W_ih (fp16)
__device__ __align__(256) float g_bias[4 * G4];            // permuted b_ih+b_hh
__device__ __align__(256) float g_xproj[2ULL * TT * BB * G4];  // gate preacts (b-major)

// ---------------- small helpers --------------------------------------------
__device__ __forceinline__ float tanhfast(float x) {
    float y; asm("tanh.approx.f32 %0, %1;" : "=f"(y) : "f"(x)); return y;
}
__device__ __forceinline__ float sigmfast(float x) {
    return fmaf(0.5f, tanhfast(0.5f * x), 0.5f);
}
__device__ __forceinline__ uint32_t smem_u32(const void* p) {
    uint32_t a;
    asm("{ .reg .u64 t; cvta.to.shared.u64 t, %1; cvt.u32.u64 %0, t; }" : "=r"(a) : "l"(p));
    return a;
}

// ---------------- mma.sync / ldmatrix / cp.async / cluster wrappers ---------
__device__ __forceinline__ void ldm4(uint32_t* r, uint32_t addr) {
    asm volatile("ldmatrix.sync.aligned.m8n8.x4.shared.b16 {%0,%1,%2,%3}, [%4];"
                 : "=r"(r[0]), "=r"(r[1]), "=r"(r[2]), "=r"(r[3]) : "r"(addr));
}
__device__ __forceinline__ void mma_f16(float* d, const uint32_t* a,
                                        uint32_t b0, uint32_t b1) {
    asm volatile(
        "mma.sync.aligned.m16n8k16.row.col.f32.f16.f16.f32 "
        "{%0,%1,%2,%3}, {%4,%5,%6,%7}, {%8,%9}, {%0,%1,%2,%3};"
        : "+f"(d[0]), "+f"(d[1]), "+f"(d[2]), "+f"(d[3])
        : "r"(a[0]), "r"(a[1]), "r"(a[2]), "r"(a[3]), "r"(b0), "r"(b1));
}
__device__ __forceinline__ void cpasync16(uint32_t dst, const void* src) {
    asm volatile("cp.async.cg.shared.global [%0], [%1], 16;" :: "r"(dst), "l"(src));
}
#define CP_COMMIT() asm volatile("cp.async.commit_group;" ::: "memory")
#define CP_WAIT(n)  asm volatile("cp.async.wait_group %0;" :: "n"(n) : "memory")
#define CLU_ARRIVE() asm volatile("barrier.cluster.arrive.aligned;" ::: "memory")
#define CLU_WAIT()   asm volatile("barrier.cluster.wait.aligned;" ::: "memory")
__device__ __forceinline__ uint32_t mapa_u32(uint32_t laddr, uint32_t rank) {
    uint32_t r;
    asm volatile("mapa.shared::cluster.u32 %0, %1, %2;" : "=r"(r) : "r"(laddr), "r"(rank));
    return r;
}
__device__ __forceinline__ void st_clu(uint32_t addr, uint32_t v) {
    asm volatile("st.shared::cluster.u32 [%0], %1;" :: "r"(addr), "r"(v));
}

// ---------------- zero only the never-written output tail (t >= lengths[b]) --
// Layer-1 lstm writes all rows t < steps(group) (zeros where masked), so only
// t >= lengths[b] needs pre-zeroing. grid = (B, T/32); block zeroes its slab.
__global__ void k_zero_out(float* __restrict__ dout, const int* __restrict__ lengths)
{
    const int b  = blockIdx.x;
    const int t0 = blockIdx.y * 32;
    const int len = lengths[b];
    if (t0 + 32 <= len) return;               // fully inside valid region
    // zero rows [max(t0,len), t0+32) of out[b, :, 512]
    const int tstart = (len > t0) ? len : t0;
    float4* base = (float4*)(dout + ((size_t)b * TT + tstart) * 512);
    const int nrows = t0 + 32 - tstart;
    const int n4 = nrows * 128;               // 512 floats = 128 float4 per row
    for (int i = threadIdx.x; i < n4; i += 256)
        base[i] = make_float4(0.f, 0.f, 0.f, 0.f);
}

// ---------------- convert x: (B,T,D) fp32 -> fp16, same order ---------------
__global__ void k_split_x(const float* __restrict__ x)
{
    int i = blockIdx.x * blockDim.x + threadIdx.x;       // float4 index
    const int N4 = MM * (DIN / 4);
    if (i >= N4) return;
    float4 v = ((const float4*)x)[i];
    __half h[4];
    h[0] = __float2half_rn(v.x); h[1] = __float2half_rn(v.y);
    h[2] = __float2half_rn(v.z); h[3] = __float2half_rn(v.w);
    ((uint2*)g_xh)[i] = *(uint2*)h;
}

// ---------------- convert + permute weights (fp16 single) -------------------
__global__ void k_split_w(const float* __restrict__ Wih, const float* __restrict__ bih,
                          const float* __restrict__ bhh)
{
    int i = blockIdx.x * blockDim.x + threadIdx.x;       // (ld, n, k4)
    if (i >= 4 * G4 * (DIN / 4)) return;
    int k4 = i & 127;
    int rest = i >> 7;
    int n = rest & (G4 - 1);
    int ld = rest >> 10;
    int r = (n & 3) * HH + (n >> 2);
    float4 v = *(const float4*)(Wih + ((size_t)ld * G4 + r) * DIN + k4 * 4);
    __half h[4];
    h[0] = __float2half_rn(v.x); h[1] = __float2half_rn(v.y);
    h[2] = __float2half_rn(v.z); h[3] = __float2half_rn(v.w);
    size_t off = ((size_t)ld * G4 + n) * DIN + k4 * 4;
    *(uint2*)(g_w + off) = *(uint2*)h;
    if (k4 == 0)
        g_bias[ld * G4 + n] = bih[ld * G4 + r] + bhh[ld * G4 + r];
}

// ---------------- mma.sync input-projection GEMM (R13: 1-term fp16, 3-stage) -
#define KC     32
#define NCH    (DIN / KC)                  // 16 chunks
#define LDS_T  40
#define ARR_B  (128 * LDS_T * 2)           // 10240
#define STG_B  (2 * ARR_B)                 // 20480  (A + W)
#define SMO_BIAS  0
#define SMO_TILES 512
#define SM_GEMM   (SMO_TILES + 3 * STG_B)  // 61952

__global__ void __launch_bounds__(256, 2) k_gemm_tc(const int* __restrict__ lengths,
                                                    int layer)
{
    const int mb  = blockIdx.y * 128;
    // tile-skip: rows are b-major (m = b*TT + t); a 128-row tile spans one b.
    {
        int b = mb >> 9;
        int t0 = mb & (TT - 1);
        if (t0 >= lengths[b]) return;     // xproj never unmasked -> skip
    }

    extern __shared__ char smx[];
    const uint32_t smb = smem_u32(smx);
    const int tid = threadIdx.x;
    const int lane = tid & 31;
    const int w   = tid >> 5;
    const int wm  = w & 1;
    const int wn  = w >> 1;
    const int dir = blockIdx.z;
    const int nb  = blockIdx.x * 128;

    const __half* Ah = layer ? g_i2h : g_xh;
    const __half* Wd = g_w + (size_t)(layer * 2 + dir) * G4 * DIN;

    float* bs = (float*)(smx + SMO_BIAS);
    if (tid < 128) bs[tid] = g_bias[(layer * 2 + dir) * G4 + nb + tid];

    auto issue_stage = [&](int ch) {
        const int kc = ch * KC;
        const uint32_t sb = smb + SMO_TILES + (ch % 3) * STG_B;
#pragma unroll
        for (int j = 0; j < 4; j++) {
            int c = tid + j * 256;
            int arr = c >> 9, rem = c & 511, row = rem >> 2, ck = rem & 3;
            uint32_t dst = sb + arr * ARR_B + row * (LDS_T * 2) + ck * 16;
            const __half* src = (arr == 0)
                ? Ah + (size_t)(mb + row) * DIN + kc + ck * 8
                : Wd + (size_t)(nb + row) * DIN + kc + ck * 8;
            cpasync16(dst, src);
        }
        CP_COMMIT();
    };

    issue_stage(0);
    issue_stage(1);

    float acc[4][4][4];
#pragma unroll
    for (int mi = 0; mi < 4; mi++)
#pragma unroll
        for (int ni = 0; ni < 4; ni++)
#pragma unroll
            for (int q = 0; q < 4; q++) acc[mi][ni][q] = 0.f;

    for (int ch = 0; ch < NCH; ch++) {
        if (ch + 1 < NCH) { CP_WAIT(1); } else { CP_WAIT(0); }
        __syncthreads();                       // all warps done with buffer (ch-1)%3
        if (ch + 2 < NCH) issue_stage(ch + 2); // safe: overwrites (ch-1)%3

        const uint32_t sA = smb + SMO_TILES + (ch % 3) * STG_B;
        const uint32_t sB = sA + ARR_B;

#pragma unroll
        for (int ks = 0; ks < 2; ks++) {
            const int k0 = ks * 16;
            const uint32_t aoff = ((lane & 15) * LDS_T + k0 + (lane >> 4) * 8) * 2;
            uint32_t ah[4][4];
#pragma unroll
            for (int mi = 0; mi < 4; mi++) {
                uint32_t ro = (wm * 64 + mi * 16) * (LDS_T * 2);
                ldm4(ah[mi], sA + ro + aoff);
            }
            uint32_t bh[2][4];
#pragma unroll
            for (int nj = 0; nj < 2; nj++) {
                uint32_t ro = (wn * 32 + nj * 16) * (LDS_T * 2);
                ldm4(bh[nj], sB + ro + aoff);
            }
#pragma unroll
            for (int mi = 0; mi < 4; mi++)
#pragma unroll
                for (int ni = 0; ni < 4; ni++) {
                    int nj = ni >> 1, hf = ni & 1;
                    mma_f16(acc[mi][ni], ah[mi], bh[nj][hf], bh[nj][hf + 2]);
                }
        }
    }
    __syncthreads();

    float* xp = g_xproj + (size_t)dir * TT * BB * G4;
    const int gid = lane >> 2, tig = lane & 3;
#pragma unroll
    for (int mi = 0; mi < 4; mi++) {
#pragma unroll
        for (int ni = 0; ni < 4; ni++) {
            int col = wn * 32 + ni * 8 + tig * 2;
            float b0 = bs[col], b1 = bs[col + 1];
            int r0 = mb + wm * 64 + mi * 16 + gid;
            float2 v0 = make_float2(acc[mi][ni][0] + b0, acc[mi][ni][1] + b1);
            float2 v1 = make_float2(acc[mi][ni][2] + b0, acc[mi][ni][3] + b1);
            *(float2*)(xp + (size_t)r0 * G4 + nb + col) = v0;
            *(float2*)(xp + (size_t)(r0 + 8) * G4 + nb + col) = v1;
        }
    }
}

// ---------------- recurrent persistent kernel (cluster + DSMEM, 16 warps) ----
// grid = 2 dir x 8 bgroup (M=16) x 8 nslice (N=128).  Cluster = the 8 nslices.
// Step-skip: lengths sorted desc -> group max = lengths[mg*16]; steps beyond it
// are provable no-ops in both directions (mask false for entire group).
#define RLDS  264                          // padded row stride (fp16 elems)
#define OW_S  0                            // W slice: 128 x 256 fp16 = 67584
#define AB_SZ (16 * RLDS * 2)              // 8448 per A buffer
#define OA_H0 (OW_S + 128 * RLDS * 2)      // 67584
#define OA_H1 (OA_H0 + AB_SZ)              // 76032
#define OS_S  (OA_H1 + AB_SZ)              // 84480  S:  16 x 132 f32
#define OS_S2 (OS_S + 16 * 132 * 4)        // 92928  S2: 16 x 132 f32
#define SM_REC (OS_S2 + 16 * 132 * 4)      // 101376

__global__ void __launch_bounds__(512) __cluster_dims__(8, 1, 1)
k_lstm(const float* __restrict__ Whh, const int* __restrict__ lengths,
       float* __restrict__ dout, int layer)
{
    extern __shared__ char smx[];
    const uint32_t smb = smem_u32(smx);
    float* S  = (float*)(smx + OS_S);
    float* S2 = (float*)(smx + OS_S2);

    const int cid = blockIdx.x >> 3;      // cluster id 0..15
    const int dir = cid >> 3;             // 0..1
    const int mg  = cid & 7;              // batch group 0..7 (M=16)
    const int ns  = blockIdx.x & 7;       // n-slice (== cluster ctarank)
    const int tid = threadIdx.x;
    const int lane = tid & 31;
    const int wid  = tid >> 5;            // 0..15
    const int wn2  = wid & 7;             // 16-col slice
    const int kh   = wid >> 3;            // K half 0/1
    const int gid = lane >> 2, tig = lane & 3;

    const float* W = Whh + (size_t)(layer * 2 + dir) * G4 * HH;

    // resident W_hh slice (128 gate cols x 256) -> smem fp16, once
    for (int idx = tid; idx < 128 * 256; idx += 512) {
        int nl = idx >> 8; int k = idx & 255;
        int n = ns * 128 + nl;
        int row = (n & 3) * HH + (n >> 2);
        *(__half*)(smx + OW_S + (nl * RLDS + k) * 2) = __float2half_rn(W[(size_t)row * HH + k]);
    }
    // zero both parities of A
    for (int idx = tid; idx < 2 * AB_SZ / 4; idx += 512)
        *(uint32_t*)(smx + OA_H0 + idx * 4) = 0;
    __syncthreads();

    // hoist W fragments: this warp's 16 cols x its K-half (8 k-iters)
    const uint32_t aoff = ((lane & 15) * RLDS + (lane >> 4) * 8 + kh * 128) * 2;
    const uint32_t bbase = (uint32_t)(wn2 * 16 * RLDS * 2);
    uint32_t bf[8][4];
#pragma unroll
    for (int ki = 0; ki < 8; ki++)
        ldm4(bf[ki], smb + OW_S + bbase + aoff + ki * 32);

    // pointwise mapping: unit u = lane (0..31), batch m = wid (0..15)
    const int u = lane;
    const int m = wid;
    const int b_glob = mg * 16 + m;
    const int u0g = ns * 32 + u;          // global unit col in A
    const int len = lengths[b_glob];

    // group-uniform step count: lengths sorted desc -> max of group = first elem
    const int steps = lengths[mg * 16];

    float cs = 0.f, hs = 0.f;

    const float* xpbase = g_xproj + (size_t)dir * TT * BB * G4;

    float4 pg;
    {
        int t0 = dir ? (steps - 1) : 0;
        pg = *(const float4*)(xpbase + ((size_t)b_glob * TT + t0) * G4 + u0g * 4);
    }

    const uint32_t laddr_off = (m * RLDS + u0g) * 2;   // even-lane threads push

    CLU_ARRIVE(); CLU_WAIT();   // zeroed A visible cluster-wide

    for (int s = 0; s < steps; s++) {
        int t = dir ? (steps - 1 - s) : s;
        const uint32_t pA = smb + ((s & 1) ? OA_H1 : OA_H0);

        // mma: partial S[16 x 128] over this warp's K half
        float acc[2][4];
#pragma unroll
        for (int ni = 0; ni < 2; ni++)
#pragma unroll
            for (int q = 0; q < 4; q++) acc[ni][q] = 0.f;

#pragma unroll
        for (int ki = 0; ki < 8; ki++) {
            uint32_t ah[4];
            ldm4(ah, pA + aoff + ki * 32);
            mma_f16(acc[0], ah, bf[ki][0], bf[ki][2]);
            mma_f16(acc[1], ah, bf[ki][1], bf[ki][3]);
        }

        // partial accumulators -> S (k-half 0) / S2 (k-half 1)
        float* Sk = kh ? S2 : S;
#pragma unroll
        for (int ni = 0; ni < 2; ni++) {
            int col = wn2 * 16 + ni * 8 + tig * 2;
            *(float2*)&Sk[gid * 132 + col] = make_float2(acc[ni][0], acc[ni][1]);
            *(float2*)&Sk[(gid + 8) * 132 + col] = make_float2(acc[ni][2], acc[ni][3]);
        }
        __syncthreads();

        // pointwise: 1 (batch m, unit u) per thread
        const bool val = (t < len);
        float4 s1 = *(const float4*)&S[m * 132 + u * 4];
        float4 s2 = *(const float4*)&S2[m * 132 + u * 4];
        float gi = sigmfast(s1.x + s2.x + pg.x);
        float gf = sigmfast(s1.y + s2.y + pg.y);
        float gg = tanhfast(s1.z + s2.z + pg.z);
        float go = sigmfast(s1.w + s2.w + pg.w);
        float cn = gf * cs + gi * gg;
        float hn = go * tanhfast(cn);
        if (val) { cs = cn; hs = hn; }
        float ov = val ? hn : 0.f;

        // pack pairs via shuffle (even lane owns units u, u+1)
        float hs2 = __shfl_down_sync(0xffffffffu, hs, 1);
        float ov2 = __shfl_down_sync(0xffffffffu, ov, 1);
        uint32_t vh = (uint32_t)__half_as_ushort(__float2half_rn(hs)) |
                      ((uint32_t)__half_as_ushort(__float2half_rn(hs2)) << 16);
        uint32_t vo = (uint32_t)__half_as_ushort(__float2half_rn(ov)) |
                      ((uint32_t)__half_as_ushort(__float2half_rn(ov2)) << 16);

        // push h (2 units = 1 u32) into all 8 cluster CTAs' A[p^1]
        if (!(lane & 1)) {
            uint32_t la = smb + ((s & 1) ? OA_H0 : OA_H1) + laddr_off;
#pragma unroll
            for (uint32_t r = 0; r < 8; r++)
                st_clu(mapa_u32(la, r), vh);
        }

        CLU_ARRIVE();   // pushes ordered/released; overlap global work with skew

        if (layer == 0) {
            if (!(lane & 1)) {
                size_t off = ((size_t)b_glob * TT + t) * DIN + dir * HH + u0g;
                *(uint32_t*)(g_i2h + off) = vo;
            }
        } else {
            dout[((size_t)b_glob * TT + t) * 512 + dir * HH + u0g] = ov;
        }
        if (s + 1 < steps) {
            int t2 = dir ? (steps - 2 - s) : (s + 1);
            pg = *(const float4*)(xpbase + ((size_t)b_glob * TT + t2) * G4 + u0g * 4);
        }

        CLU_WAIT();     // peers' pushes visible; also full block barrier
    }

    // final h_n / c_n (coalesced: lane-major units)
    {
        size_t o = (size_t)((layer * 2 + dir) * BB + b_glob) * HH + u0g;
        dout[HN_OFF + o] = hs;
        dout[CN_OFF + o] = cs;
    }
}

// ---------------- launch -----------------------------------------------------
extern "C" void kernel_launch(void* const* d_in, const int* in_sizes, int n_in,
                              void* d_out, int out_size)
{
    const float* x   = (const float*)d_in[0];
    const int*   len = (const int*)d_in[1];
    const float* Wih = (const float*)d_in[2];
    const float* Whh = (const float*)d_in[3];
    const float* bih = (const float*)d_in[4];
    const float* bhh = (const float*)d_in[5];
    float* out = (float*)d_out;

    cudaFuncSetAttribute(k_lstm, cudaFuncAttributeMaxDynamicSharedMemorySize, SM_REC);
    cudaFuncSetAttribute(k_gemm_tc, cudaFuncAttributeMaxDynamicSharedMemorySize, SM_GEMM);

    // zero only the never-written output tail (t >= lengths[b])
    k_zero_out<<<dim3(BB, TT / 32), 256>>>(out, len);

    k_split_x<<<(MM * (DIN / 4) + 255) / 256, 256>>>(x);
    k_split_w<<<(4 * G4 * (DIN / 4) + 255) / 256, 256>>>(Wih, bih, bhh);

    k_gemm_tc<<<dim3(G4 / 128, MM / 128, 2), 256, SM_GEMM>>>(len, 0);
    k_lstm<<<128, 512, SM_REC>>>(Whh, len, out, 0);
    k_gemm_tc<<<dim3(G4 / 128, MM / 128, 2), 256, SM_GEMM>>>(len, 1);
    k_lstm<<<128, 512, SM_REC>>>(Whh, len, out, 1);
}